// round 9
// baseline (speedup 1.0000x reference)
#include <cuda_runtime.h>
#include <cuda_fp16.h>
#include <math.h>

// Problem shapes (fixed for this dataset)
#define BB 16
#define NN 2048
#define FF 64
#define EE 24576          // edges per batch (N*M = 2048*12)
#define CC 128            // bond dim
#define TOTAL_E (BB*EE)   // 393216

#define A_SCALE 16384.0f          // 2^14 — exact; BN is affine-invariant
#define A_INVSCALE (1.0f/16384.0f)

// Edge-pass decomposition: 8192 warps * 48 edges = TOTAL_E exactly
#define EP_BLOCKS 1024
#define EP_WARPS  (EP_BLOCKS * 8)
#define EP_CHUNK  (TOTAL_E / EP_WARPS)     // 48

// Streaming out pass: 1536*256 threads * 32 uint2-units = TOTAL_E*CC/4 exactly
#define OUT_BLOCKS 1536
#define OUT_UNITS  (TOTAL_E * CC / 4)      // 12,582,912
#define OUT_ITERS  (OUT_UNITS / (OUT_BLOCKS * 256))   // 32

// Scratch (static device globals — no runtime allocation allowed)
__device__ int    g_count[2][BB][NN];                   // overwritten each call
__device__ float  g_den[2][BB][FF];                     // L1 denominators (raw sums)
__device__ __align__(16) __half g_Ah[2][BB][NN][CC];    // scaled fp16 GEMM results (16.7 MB)
__device__ __align__(16) __half g_z[TOTAL_E][CC];       // cached fp16 z' (100.7 MB)
__device__ float  g_sum[CC];                            // sums of scaled z'
__device__ float  g_sq[CC];                             // sums of scaled z'^2

// ---- Blackwell packed-f32 helpers -----------------------------------------
__device__ __forceinline__ void ffma2(unsigned long long& d,
                                      unsigned long long a, unsigned long long b) {
    asm("fma.rn.f32x2 %0, %1, %2, %0;" : "+l"(d) : "l"(a), "l"(b));
}
__device__ __forceinline__ unsigned long long pack2(float x) {
    unsigned long long r;
    asm("mov.b64 %0, {%1, %1};" : "=l"(r) : "f"(x));
    return r;
}
__device__ __forceinline__ float2 unpack2(unsigned long long v) {
    float2 f;
    asm("mov.b64 {%0, %1}, %2;" : "=f"(f.x), "=f"(f.y) : "l"(v));
    return f;
}
__device__ __forceinline__ float tanh_fast(float x) {
    asm("tanh.approx.f32 %0, %0;" : "+f"(x));
    return x;
}

// ---------------------------------------------------------------------------
// Zero only the accumulators (g_count is fully overwritten by count_kernel).
__global__ void zero_kernel() {
    int i = blockIdx.x * blockDim.x + threadIdx.x;
    if (i < 2 * BB * FF) (&g_den[0][0][0])[i] = 0.f;
    if (i < CC) { g_sum[i] = 0.f; g_sq[i] = 0.f; }
}

// Per-batch shared-memory histogram; bulk store, no global atomics.
__global__ void count_kernel(const int* __restrict__ adj) {
    __shared__ int h[2][NN];
    int b = blockIdx.x;
    int tid = threadIdx.x;
    for (int i = tid; i < 2 * NN; i += 512) (&h[0][0])[i] = 0;
    __syncthreads();
    const int2* ap = (const int2*)adj + (size_t)b * EE;
    for (int k = tid; k < EE; k += 512) {
        int2 ad = ap[k];
        atomicAdd(&h[0][ad.x & (NN - 1)], 1);
        atomicAdd(&h[1][ad.y & (NN - 1)], 1);
    }
    __syncthreads();
    for (int i = tid; i < NN; i += 512) {
        g_count[0][b][i] = h[0][i];
        g_count[1][b][i] = h[1][i];
    }
}

// Both-slot partial denominators: grid = 16*8 = 128 blocks, 256 nodes each.
__global__ void denom_kernel(const float* __restrict__ atom) {
    int bx = blockIdx.x;
    int part = bx & 7, b = bx >> 3;
    int tid = threadIdx.x;
    int f = tid & 63, sub = tid >> 6;        // 4 row sub-partitions
    int nbase = part * 256;
    float acc0 = 0.f, acc1 = 0.f;
    const float* ab = atom + ((size_t)b * NN + nbase) * FF;
    for (int n = sub; n < 256; n += 4) {
        float v = fabsf(ab[n * FF + f]);
        int c0 = g_count[0][b][nbase + n];
        int c1 = g_count[1][b][nbase + n];
        acc0 += (float)c0 * v;
        acc1 += (float)c1 * v;
    }
    __shared__ float sh[2][256];
    sh[0][tid] = acc0;
    sh[1][tid] = acc1;
    __syncthreads();
    if (tid < 64) {
        float t = sh[0][tid] + sh[0][tid + 64] + sh[0][tid + 128] + sh[0][tid + 192];
        atomicAdd(&g_den[0][b][tid], t);
    } else if (tid < 128) {
        int ff = tid - 64;
        float t = sh[1][ff] + sh[1][ff + 64] + sh[1][ff + 128] + sh[1][ff + 192];
        atomicAdd(&g_den[1][b][ff], t);
    }
}

// A'_s[b,n,c] = A_SCALE * sum_f atom[b,n,f] * (W[s*64+f,c] / den_s[b,f])
// Packed fma.rn.f32x2 inner product. Grid = 1024.
__global__ void gemm_kernel(const float* __restrict__ atom, const float* __restrict__ W) {
    int bx = blockIdx.x;
    int tile = bx & 31, s = (bx >> 5) & 1, b = bx >> 6;
    int n0 = tile * 64;
    __shared__ __align__(16) float a_sh[64][FF];
    __shared__ __align__(16) float w_sh[FF * CC];
    __shared__ float rsh[FF];
    int tid = threadIdx.x;

    if (tid < FF) rsh[tid] = 1.0f / fmaxf(g_den[s][b][tid], 1e-12f);
    __syncthreads();
    const float* wb = W + s * FF * CC;
#pragma unroll
    for (int k = tid * 4; k < FF * CC; k += 1024) {
        float4 wv = *(const float4*)&wb[k];
        float r = rsh[k >> 7];
        wv.x *= r; wv.y *= r; wv.z *= r; wv.w *= r;
        *(float4*)&w_sh[k] = wv;
    }
    const float* ab = atom + ((size_t)b * NN + n0) * FF;
#pragma unroll
    for (int k = tid * 4; k < 64 * FF; k += 1024)
        *(float4*)((&a_sh[0][0]) + k) = *(const float4*)(ab + k);
    __syncthreads();

    int c4 = (tid & 31) * 4;     // column slice (4 channels = 2 packed pairs)
    int r8 = (tid >> 5) * 8;     // row base per warp
    unsigned long long acc0[8], acc1[8];
#pragma unroll
    for (int i = 0; i < 8; i++) { acc0[i] = 0ULL; acc1[i] = 0ULL; }

#pragma unroll 4
    for (int f0 = 0; f0 < FF; f0 += 4) {
        ulonglong2 w0 = *(ulonglong2*)&w_sh[(f0 + 0) * CC + c4];
        ulonglong2 w1 = *(ulonglong2*)&w_sh[(f0 + 1) * CC + c4];
        ulonglong2 w2 = *(ulonglong2*)&w_sh[(f0 + 2) * CC + c4];
        ulonglong2 w3 = *(ulonglong2*)&w_sh[(f0 + 3) * CC + c4];
#pragma unroll
        for (int i = 0; i < 8; i++) {
            float4 a = *(float4*)&a_sh[r8 + i][f0];
            unsigned long long ax = pack2(a.x), ay = pack2(a.y);
            unsigned long long az = pack2(a.z), aw = pack2(a.w);
            ffma2(acc0[i], ax, w0.x); ffma2(acc1[i], ax, w0.y);
            ffma2(acc0[i], ay, w1.x); ffma2(acc1[i], ay, w1.y);
            ffma2(acc0[i], az, w2.x); ffma2(acc1[i], az, w2.y);
            ffma2(acc0[i], aw, w3.x); ffma2(acc1[i], aw, w3.y);
        }
    }
    __half* ob = &g_Ah[s][b][n0][0];
#pragma unroll
    for (int i = 0; i < 8; i++) {
        float2 p0 = unpack2(acc0[i]);
        float2 p1 = unpack2(acc1[i]);
        __half2 h01 = __floats2half2_rn(p0.x * A_SCALE, p0.y * A_SCALE);
        __half2 h23 = __floats2half2_rn(p1.x * A_SCALE, p1.y * A_SCALE);
        uint2 u = make_uint2(*(unsigned*)&h01, *(unsigned*)&h23);
        *(uint2*)&ob[(size_t)(r8 + i) * CC + c4] = u;
    }
}

// Gather z' = A'0[i0]+A'1[i1], cache rounded fp16 z' to g_z, accumulate stats
// on the SAME rounded values (keeps BN self-consistent with out pass).
__global__ void fuse_kernel(const int* __restrict__ adj) {
    int tid = threadIdx.x;
    int lane = tid & 31;
    int warp_g = (blockIdx.x * blockDim.x + tid) >> 5;
    int e0 = warp_g * EP_CHUNK;
    float s0 = 0, s1 = 0, s2 = 0, s3 = 0, q0 = 0, q1 = 0, q2 = 0, q3 = 0;
#pragma unroll 4
    for (int k = 0; k < EP_CHUNK; k++) {
        int e = e0 + k;
        int b = e / EE;
        int2 ad = *(const int2*)(adj + 2 * (size_t)e);
        const uint2* r0 = (const uint2*)g_Ah[0][b][ad.x & (NN - 1)];
        const uint2* r1 = (const uint2*)g_Ah[1][b][ad.y & (NN - 1)];
        uint2 u0 = r0[lane], u1 = r1[lane];
        float2 a0 = __half22float2(*(__half2*)&u0.x);
        float2 a1 = __half22float2(*(__half2*)&u0.y);
        float2 b0 = __half22float2(*(__half2*)&u1.x);
        float2 b1 = __half22float2(*(__half2*)&u1.y);
        __half2 h01 = __floats2half2_rn(a0.x + b0.x, a0.y + b0.y);
        __half2 h23 = __floats2half2_rn(a1.x + b1.x, a1.y + b1.y);
        *(uint2*)&g_z[e][lane * 4] = make_uint2(*(unsigned*)&h01, *(unsigned*)&h23);
        float2 zr0 = __half22float2(h01);
        float2 zr1 = __half22float2(h23);
        s0 += zr0.x; q0 = fmaf(zr0.x, zr0.x, q0);
        s1 += zr0.y; q1 = fmaf(zr0.y, zr0.y, q1);
        s2 += zr1.x; q2 = fmaf(zr1.x, zr1.x, q2);
        s3 += zr1.y; q3 = fmaf(zr1.y, zr1.y, q3);
    }
    __shared__ float sh[8 * CC];
    int w = tid >> 5;
    sh[w * CC + lane * 4 + 0] = s0;
    sh[w * CC + lane * 4 + 1] = s1;
    sh[w * CC + lane * 4 + 2] = s2;
    sh[w * CC + lane * 4 + 3] = s3;
    __syncthreads();
    if (tid < CC) {
        float t = 0;
#pragma unroll
        for (int i = 0; i < 8; i++) t += sh[i * CC + tid];
        atomicAdd(&g_sum[tid], t);
    }
    __syncthreads();
    sh[w * CC + lane * 4 + 0] = q0;
    sh[w * CC + lane * 4 + 1] = q1;
    sh[w * CC + lane * 4 + 2] = q2;
    sh[w * CC + lane * 4 + 3] = q3;
    __syncthreads();
    if (tid < CC) {
        float t = 0;
#pragma unroll
        for (int i = 0; i < 8; i++) t += sh[i * CC + tid];
        atomicAdd(&g_sq[tid], t);
    }
}

// Streaming final pass: read cached z' sequentially, BN + tanh, write out.
// idx % 32 is invariant per thread (stride multiple of 32) -> channel slice fixed.
__global__ void out_kernel(const float* __restrict__ gamma,
                           const float* __restrict__ beta,
                           float* __restrict__ out) {
    __shared__ __align__(16) float ssc[CC];
    __shared__ __align__(16) float ssf[CC];
    int tid = threadIdx.x;
    if (tid < CC) {
        float inv = 1.0f / (float)TOTAL_E;
        float mean_u = g_sum[tid] * inv * A_INVSCALE;
        float ez2_u  = g_sq[tid] * inv * (A_INVSCALE * A_INVSCALE);
        float var = fmaxf(ez2_u - mean_u * mean_u, 0.0f);
        float sc = __ldg(&gamma[tid]) * rsqrtf(var + 1e-5f);
        ssc[tid] = sc * A_INVSCALE;              // applied to scaled z'
        ssf[tid] = __ldg(&beta[tid]) - mean_u * sc;
    }
    __syncthreads();
    int c4 = (tid & 31) * 4;
    float4 sc = *(const float4*)&ssc[c4];
    float4 sf = *(const float4*)&ssf[c4];
    const uint2* zp = (const uint2*)&g_z[0][0];
    int idx = blockIdx.x * 256 + tid;
    const int stride = OUT_BLOCKS * 256;
#pragma unroll 4
    for (int it = 0; it < OUT_ITERS; it++, idx += stride) {
        uint2 u = zp[idx];
        float2 z0 = __half22float2(*(__half2*)&u.x);
        float2 z1 = __half22float2(*(__half2*)&u.y);
        float4 o;
        o.x = tanh_fast(fmaf(z0.x, sc.x, sf.x));
        o.y = tanh_fast(fmaf(z0.y, sc.y, sf.y));
        o.z = tanh_fast(fmaf(z1.x, sc.z, sf.z));
        o.w = tanh_fast(fmaf(z1.y, sc.w, sf.w));
        *(float4*)(out + (size_t)idx * 4) = o;
    }
}

extern "C" void kernel_launch(void* const* d_in, const int* in_sizes, int n_in,
                              void* d_out, int out_size) {
    const float* atom      = (const float*)d_in[0];
    const int*   adj       = (const int*)d_in[1];    // int32 (JAX default x64-off)
    const float* W         = (const float*)d_in[2];
    // d_in[3] (bias) is mathematically cancelled by BatchNorm -> unused
    const float* gamma     = (const float*)d_in[4];
    const float* beta      = (const float*)d_in[5];
    float* out             = (float*)d_out;

    zero_kernel<<<9, 256>>>();
    count_kernel<<<BB, 512>>>(adj);
    denom_kernel<<<128, 256>>>(atom);
    gemm_kernel<<<1024, 256>>>(atom, W);
    fuse_kernel<<<EP_BLOCKS, 256>>>(adj);
    out_kernel<<<OUT_BLOCKS, 256>>>(gamma, beta, out);
}

// round 11
// speedup vs baseline: 1.0855x; 1.0855x over previous
#include <cuda_runtime.h>
#include <cuda_fp16.h>
#include <math.h>

// Problem shapes (fixed for this dataset)
#define BB 16
#define NN 2048
#define FF 64
#define EE 24576          // edges per batch (N*M = 2048*12)
#define CC 128            // bond dim
#define TOTAL_E (BB*EE)   // 393216

#define A_SCALE 16384.0f          // 2^14 — exact; BN is affine-invariant
#define A_INVSCALE (1.0f/16384.0f)

// Edge-pass decomposition: 8192 warps * 48 edges = TOTAL_E exactly
#define EP_BLOCKS 1024
#define EP_WARPS  (EP_BLOCKS * 8)
#define EP_CHUNK  (TOTAL_E / EP_WARPS)     // 48

// Scratch (static device globals — no runtime allocation allowed)
__device__ int    g_count[2][BB][NN];                   // overwritten each call
__device__ float  g_den[2][BB][FF];                     // L1 denominators (raw sums)
__device__ __align__(16) __half g_Ah[2][BB][NN][CC];    // scaled fp16 GEMM results (16.7 MB, L2-hot)
__device__ float  g_sum[CC];                            // sums of scaled z'
__device__ float  g_sq[CC];                             // sums of scaled z'^2

// ---- Blackwell packed-f32 helpers -----------------------------------------
__device__ __forceinline__ void ffma2(unsigned long long& d,
                                      unsigned long long a, unsigned long long b) {
    asm("fma.rn.f32x2 %0, %1, %2, %0;" : "+l"(d) : "l"(a), "l"(b));
}
__device__ __forceinline__ unsigned long long pack2(float x) {
    unsigned long long r;
    asm("mov.b64 %0, {%1, %1};" : "=l"(r) : "f"(x));
    return r;
}
__device__ __forceinline__ float2 unpack2(unsigned long long v) {
    float2 f;
    asm("mov.b64 {%0, %1}, %2;" : "=f"(f.x), "=f"(f.y) : "l"(v));
    return f;
}
__device__ __forceinline__ float tanh_fast(float x) {
    asm("tanh.approx.f32 %0, %0;" : "+f"(x));
    return x;
}

// ---------------------------------------------------------------------------
// Zero only the accumulators (g_count is fully overwritten by count_kernel).
__global__ void zero_kernel() {
    int i = blockIdx.x * blockDim.x + threadIdx.x;
    if (i < 2 * BB * FF) (&g_den[0][0][0])[i] = 0.f;
    if (i < CC) { g_sum[i] = 0.f; g_sq[i] = 0.f; }
}

// Per-batch shared-memory histogram; bulk store, no global atomics.
__global__ void count_kernel(const int* __restrict__ adj) {
    __shared__ int h[2][NN];
    int b = blockIdx.x;
    int tid = threadIdx.x;
    for (int i = tid; i < 2 * NN; i += 512) (&h[0][0])[i] = 0;
    __syncthreads();
    const int2* ap = (const int2*)adj + (size_t)b * EE;
    for (int k = tid; k < EE; k += 512) {
        int2 ad = ap[k];
        atomicAdd(&h[0][ad.x & (NN - 1)], 1);
        atomicAdd(&h[1][ad.y & (NN - 1)], 1);
    }
    __syncthreads();
    for (int i = tid; i < NN; i += 512) {
        g_count[0][b][i] = h[0][i];
        g_count[1][b][i] = h[1][i];
    }
}

// Both-slot partial denominators: grid = 16*8 = 128 blocks, 256 nodes each.
__global__ void denom_kernel(const float* __restrict__ atom) {
    int bx = blockIdx.x;
    int part = bx & 7, b = bx >> 3;
    int tid = threadIdx.x;
    int f = tid & 63, sub = tid >> 6;        // 4 row sub-partitions
    int nbase = part * 256;
    float acc0 = 0.f, acc1 = 0.f;
    const float* ab = atom + ((size_t)b * NN + nbase) * FF;
    for (int n = sub; n < 256; n += 4) {
        float v = fabsf(ab[n * FF + f]);
        int c0 = g_count[0][b][nbase + n];
        int c1 = g_count[1][b][nbase + n];
        acc0 += (float)c0 * v;
        acc1 += (float)c1 * v;
    }
    __shared__ float sh[2][256];
    sh[0][tid] = acc0;
    sh[1][tid] = acc1;
    __syncthreads();
    if (tid < 64) {
        float t = sh[0][tid] + sh[0][tid + 64] + sh[0][tid + 128] + sh[0][tid + 192];
        atomicAdd(&g_den[0][b][tid], t);
    } else if (tid < 128) {
        int ff = tid - 64;
        float t = sh[1][ff] + sh[1][ff + 64] + sh[1][ff + 128] + sh[1][ff + 192];
        atomicAdd(&g_den[1][b][ff], t);
    }
}

// A'_s[b,n,c] = A_SCALE * sum_f atom[b,n,f] * (W[s*64+f,c] / den_s[b,f])
// 128 threads/block, 16 rows per warp: amortizes lane-distinct w LDS over 2x
// rows (LDS cyc per FFMA2 0.52 -> 0.27, FMA-bound). smem = 48 KB exactly.
__global__ void gemm_kernel(const float* __restrict__ atom, const float* __restrict__ W) {
    int bx = blockIdx.x;
    int tile = bx & 31, s = (bx >> 5) & 1, b = bx >> 6;
    int n0 = tile * 64;
    __shared__ __align__(16) float a_sh[64][FF];       // 16 KB
    __shared__ __align__(16) float w_sh[FF * CC];      // 32 KB
    int tid = threadIdx.x;

    // w_sh[f][c] = W[s*64+f][c] * rden_s[b][f]  (rden via L1-hot __ldg)
    const float* wb = W + s * FF * CC;
    const float* dn = &g_den[s][b][0];
#pragma unroll
    for (int k = tid * 4; k < FF * CC; k += 512) {
        float4 wv = *(const float4*)&wb[k];
        float r = 1.0f / fmaxf(__ldg(&dn[k >> 7]), 1e-12f);
        wv.x *= r; wv.y *= r; wv.z *= r; wv.w *= r;
        *(float4*)&w_sh[k] = wv;
    }
    const float* ab = atom + ((size_t)b * NN + n0) * FF;
#pragma unroll
    for (int k = tid * 4; k < 64 * FF; k += 512)
        *(float4*)((&a_sh[0][0]) + k) = *(const float4*)(ab + k);
    __syncthreads();

    int c4 = (tid & 31) * 4;      // 4 channels = 2 packed pairs per lane
    int r16 = (tid >> 5) * 16;    // 16 rows per warp
    unsigned long long acc0[16], acc1[16];
#pragma unroll
    for (int i = 0; i < 16; i++) { acc0[i] = 0ULL; acc1[i] = 0ULL; }

#pragma unroll 4
    for (int f0 = 0; f0 < FF; f0 += 2) {
        ulonglong2 w0 = *(ulonglong2*)&w_sh[(f0 + 0) * CC + c4];
        ulonglong2 w1 = *(ulonglong2*)&w_sh[(f0 + 1) * CC + c4];
#pragma unroll
        for (int i = 0; i < 16; i++) {
            float2 a = *(float2*)&a_sh[r16 + i][f0];   // lane-invariant broadcast
            unsigned long long ax = pack2(a.x), ay = pack2(a.y);
            ffma2(acc0[i], ax, w0.x); ffma2(acc1[i], ax, w0.y);
            ffma2(acc0[i], ay, w1.x); ffma2(acc1[i], ay, w1.y);
        }
    }
    __half* ob = &g_Ah[s][b][n0][0];
#pragma unroll
    for (int i = 0; i < 16; i++) {
        float2 p0 = unpack2(acc0[i]);
        float2 p1 = unpack2(acc1[i]);
        __half2 h01 = __floats2half2_rn(p0.x * A_SCALE, p0.y * A_SCALE);
        __half2 h23 = __floats2half2_rn(p1.x * A_SCALE, p1.y * A_SCALE);
        uint2 u = make_uint2(*(unsigned*)&h01, *(unsigned*)&h23);
        *(uint2*)&ob[(size_t)(r16 + i) * CC + c4] = u;
    }
}

// Per-channel sum and sum-of-squares of z' = A'0[i0] + A'1[i1] (L2-hot gather)
__global__ void stats_kernel(const int* __restrict__ adj) {
    int tid = threadIdx.x;
    int lane = tid & 31;
    int warp_g = (blockIdx.x * blockDim.x + tid) >> 5;
    int e0 = warp_g * EP_CHUNK;
    float s0 = 0, s1 = 0, s2 = 0, s3 = 0, q0 = 0, q1 = 0, q2 = 0, q3 = 0;
#pragma unroll 4
    for (int k = 0; k < EP_CHUNK; k++) {
        int e = e0 + k;
        int b = e / EE;
        int2 ad = *(const int2*)(adj + 2 * (size_t)e);
        const uint2* r0 = (const uint2*)g_Ah[0][b][ad.x & (NN - 1)];
        const uint2* r1 = (const uint2*)g_Ah[1][b][ad.y & (NN - 1)];
        uint2 u0 = r0[lane], u1 = r1[lane];
        float2 a0 = __half22float2(*(__half2*)&u0.x);
        float2 a1 = __half22float2(*(__half2*)&u0.y);
        float2 b0 = __half22float2(*(__half2*)&u1.x);
        float2 b1 = __half22float2(*(__half2*)&u1.y);
        float z;
        z = a0.x + b0.x; s0 += z; q0 = fmaf(z, z, q0);
        z = a0.y + b0.y; s1 += z; q1 = fmaf(z, z, q1);
        z = a1.x + b1.x; s2 += z; q2 = fmaf(z, z, q2);
        z = a1.y + b1.y; s3 += z; q3 = fmaf(z, z, q3);
    }
    __shared__ float sh[8 * CC];
    int w = tid >> 5;
    sh[w * CC + lane * 4 + 0] = s0;
    sh[w * CC + lane * 4 + 1] = s1;
    sh[w * CC + lane * 4 + 2] = s2;
    sh[w * CC + lane * 4 + 3] = s3;
    __syncthreads();
    if (tid < CC) {
        float t = 0;
#pragma unroll
        for (int i = 0; i < 8; i++) t += sh[i * CC + tid];
        atomicAdd(&g_sum[tid], t);
    }
    __syncthreads();
    sh[w * CC + lane * 4 + 0] = q0;
    sh[w * CC + lane * 4 + 1] = q1;
    sh[w * CC + lane * 4 + 2] = q2;
    sh[w * CC + lane * 4 + 3] = q3;
    __syncthreads();
    if (tid < CC) {
        float t = 0;
#pragma unroll
        for (int i = 0; i < 8; i++) t += sh[i * CC + tid];
        atomicAdd(&g_sq[tid], t);
    }
}

// Final pass: gather (L2-hot), BN (finalize folded in), tanh.approx, store.
__global__ void out_kernel(const int* __restrict__ adj,
                           const float* __restrict__ gamma,
                           const float* __restrict__ beta,
                           float* __restrict__ out) {
    __shared__ __align__(16) float ssc[CC];
    __shared__ __align__(16) float ssf[CC];
    int tid = threadIdx.x;
    if (tid < CC) {
        // stats were accumulated on z' = 2^14 z; unscale exactly before eps.
        float inv = 1.0f / (float)TOTAL_E;
        float mean_u = g_sum[tid] * inv * A_INVSCALE;
        float ez2_u  = g_sq[tid] * inv * (A_INVSCALE * A_INVSCALE);
        float var = fmaxf(ez2_u - mean_u * mean_u, 0.0f);
        float sc = __ldg(&gamma[tid]) * rsqrtf(var + 1e-5f);
        ssc[tid] = sc * A_INVSCALE;              // applied to scaled z'
        ssf[tid] = __ldg(&beta[tid]) - mean_u * sc;
    }
    __syncthreads();
    int lane = tid & 31;
    int warp_g = (blockIdx.x * blockDim.x + tid) >> 5;
    int e0 = warp_g * EP_CHUNK;
    float4 sc = *(const float4*)&ssc[lane * 4];
    float4 sf = *(const float4*)&ssf[lane * 4];
#pragma unroll 4
    for (int k = 0; k < EP_CHUNK; k++) {
        int e = e0 + k;
        int b = e / EE;
        int2 ad = *(const int2*)(adj + 2 * (size_t)e);
        const uint2* r0 = (const uint2*)g_Ah[0][b][ad.x & (NN - 1)];
        const uint2* r1 = (const uint2*)g_Ah[1][b][ad.y & (NN - 1)];
        uint2 u0 = r0[lane], u1 = r1[lane];
        float2 a0 = __half22float2(*(__half2*)&u0.x);
        float2 a1 = __half22float2(*(__half2*)&u0.y);
        float2 b0 = __half22float2(*(__half2*)&u1.x);
        float2 b1 = __half22float2(*(__half2*)&u1.y);
        float4 o;
        o.x = tanh_fast(fmaf(a0.x + b0.x, sc.x, sf.x));
        o.y = tanh_fast(fmaf(a0.y + b0.y, sc.y, sf.y));
        o.z = tanh_fast(fmaf(a1.x + b1.x, sc.z, sf.z));
        o.w = tanh_fast(fmaf(a1.y + b1.y, sc.w, sf.w));
        *(float4*)(out + (size_t)e * CC + lane * 4) = o;
    }
}

extern "C" void kernel_launch(void* const* d_in, const int* in_sizes, int n_in,
                              void* d_out, int out_size) {
    const float* atom      = (const float*)d_in[0];
    const int*   adj       = (const int*)d_in[1];    // int32 (JAX default x64-off)
    const float* W         = (const float*)d_in[2];
    // d_in[3] (bias) is mathematically cancelled by BatchNorm -> unused
    const float* gamma     = (const float*)d_in[4];
    const float* beta      = (const float*)d_in[5];
    float* out             = (float*)d_out;

    zero_kernel<<<9, 256>>>();
    count_kernel<<<BB, 512>>>(adj);
    denom_kernel<<<128, 256>>>(atom);
    gemm_kernel<<<1024, 128>>>(atom, W);
    stats_kernel<<<EP_BLOCKS, 256>>>(adj);
    out_kernel<<<EP_BLOCKS, 256>>>(adj, gamma, beta, out);
}

// round 15
// speedup vs baseline: 1.1638x; 1.0722x over previous
#include <cuda_runtime.h>
#include <cuda_fp16.h>
#include <math.h>

// Problem shapes (fixed for this dataset)
#define BB 16
#define NN 2048
#define FF 64
#define EE 24576          // edges per batch (N*M = 2048*12)
#define CC 128            // bond dim
#define TOTAL_E (BB*EE)   // 393216

#define A_SCALE 16384.0f          // 2^14 — exact; BN is affine-invariant
#define A_INVSCALE (1.0f/16384.0f)

// Edge-pass decomposition: 8192 warps * 48 edges = TOTAL_E exactly.
// 48 divides EE -> every warp's 48 edges are in ONE batch (b loop-invariant).
#define EP_BLOCKS 1024
#define EP_WARPS  (EP_BLOCKS * 8)
#define EP_CHUNK  (TOTAL_E / EP_WARPS)     // 48

// Scratch (static device globals — no runtime allocation allowed)
__device__ int    g_count[2][BB][NN];                   // overwritten each call
__device__ float  g_den[2][BB][FF];                     // L1 denominators (raw sums)
__device__ __align__(16) __half g_Ah[2][BB][NN][CC];    // scaled fp16 GEMM results (16.7 MB, L2-hot)
__device__ float  g_sum[CC];                            // sums of scaled z'
__device__ float  g_sq[CC];                             // sums of scaled z'^2

// ---- Blackwell packed-f32 helpers -----------------------------------------
__device__ __forceinline__ void ffma2(unsigned long long& d,
                                      unsigned long long a, unsigned long long b) {
    asm("fma.rn.f32x2 %0, %1, %2, %0;" : "+l"(d) : "l"(a), "l"(b));
}
__device__ __forceinline__ unsigned long long pack2(float x) {
    unsigned long long r;
    asm("mov.b64 %0, {%1, %1};" : "=l"(r) : "f"(x));
    return r;
}
__device__ __forceinline__ float2 unpack2(unsigned long long v) {
    float2 f;
    asm("mov.b64 {%0, %1}, %2;" : "=f"(f.x), "=f"(f.y) : "l"(v));
    return f;
}
__device__ __forceinline__ float tanh_fast(float x) {
    asm("tanh.approx.f32 %0, %0;" : "+f"(x));
    return x;
}

// ---------------------------------------------------------------------------
// Zero only the accumulators (g_count is fully overwritten by count_kernel).
__global__ void zero_kernel() {
    int i = blockIdx.x * blockDim.x + threadIdx.x;
    if (i < 2 * BB * FF) (&g_den[0][0][0])[i] = 0.f;
    if (i < CC) { g_sum[i] = 0.f; g_sq[i] = 0.f; }
}

// Per-batch shared-memory histogram; bulk store, no global atomics.
__global__ void count_kernel(const int* __restrict__ adj) {
    __shared__ int h[2][NN];
    int b = blockIdx.x;
    int tid = threadIdx.x;
    for (int i = tid; i < 2 * NN; i += 512) (&h[0][0])[i] = 0;
    __syncthreads();
    const int2* ap = (const int2*)adj + (size_t)b * EE;
    for (int k = tid; k < EE; k += 512) {
        int2 ad = ap[k];
        atomicAdd(&h[0][ad.x & (NN - 1)], 1);
        atomicAdd(&h[1][ad.y & (NN - 1)], 1);
    }
    __syncthreads();
    for (int i = tid; i < NN; i += 512) {
        g_count[0][b][i] = h[0][i];
        g_count[1][b][i] = h[1][i];
    }
}

// Both-slot partial denominators: grid = 16*8 = 128 blocks, 256 nodes each.
__global__ void denom_kernel(const float* __restrict__ atom) {
    int bx = blockIdx.x;
    int part = bx & 7, b = bx >> 3;
    int tid = threadIdx.x;
    int f = tid & 63, sub = tid >> 6;        // 4 row sub-partitions
    int nbase = part * 256;
    float acc0 = 0.f, acc1 = 0.f;
    const float* ab = atom + ((size_t)b * NN + nbase) * FF;
    for (int n = sub; n < 256; n += 4) {
        float v = fabsf(ab[n * FF + f]);
        int c0 = g_count[0][b][nbase + n];
        int c1 = g_count[1][b][nbase + n];
        acc0 += (float)c0 * v;
        acc1 += (float)c1 * v;
    }
    __shared__ float sh[2][256];
    sh[0][tid] = acc0;
    sh[1][tid] = acc1;
    __syncthreads();
    if (tid < 64) {
        float t = sh[0][tid] + sh[0][tid + 64] + sh[0][tid + 128] + sh[0][tid + 192];
        atomicAdd(&g_den[0][b][tid], t);
    } else if (tid < 128) {
        int ff = tid - 64;
        float t = sh[1][ff] + sh[1][ff + 64] + sh[1][ff + 128] + sh[1][ff + 192];
        atomicAdd(&g_den[1][b][ff], t);
    }
}

// A'_s[b,n,c] = A_SCALE * sum_f atom[b,n,f] * (W[s*64+f,c] / den_s[b,f])
// R8 inner shape (256 thr, 8 rows/warp, regs~75 -> 3 CTAs/SM) with PAIRED
// 64-row tiles per block: w_sh fill amortized 2x, grid 512 (~1.15 waves).
__global__ void gemm_kernel(const float* __restrict__ atom, const float* __restrict__ W) {
    int bx = blockIdx.x;
    int pair = bx & 15, s = (bx >> 4) & 1, b = bx >> 5;
    int n0 = pair * 128;
    __shared__ __align__(16) float a_sh[64][FF];       // 16 KB
    __shared__ __align__(16) float w_sh[FF * CC];      // 32 KB
    int tid = threadIdx.x;

    // w_sh[f][c] = W[s*64+f][c] * rden_s[b][f]  (once per block)
    const float* wb = W + s * FF * CC;
    const float* dn = &g_den[s][b][0];
#pragma unroll
    for (int k = tid * 4; k < FF * CC; k += 1024) {
        float4 wv = *(const float4*)&wb[k];
        float r = 1.0f / fmaxf(__ldg(&dn[k >> 7]), 1e-12f);
        wv.x *= r; wv.y *= r; wv.z *= r; wv.w *= r;
        *(float4*)&w_sh[k] = wv;
    }

    int c4 = (tid & 31) * 4;     // column slice (4 channels = 2 packed pairs)
    int r8 = (tid >> 5) * 8;     // row base per warp

#pragma unroll 1
    for (int half = 0; half < 2; half++) {
        const float* ab = atom + ((size_t)b * NN + n0 + half * 64) * FF;
        __syncthreads();          // w_sh ready / prior-half a_sh reads done
#pragma unroll
        for (int k = tid * 4; k < 64 * FF; k += 1024)
            *(float4*)((&a_sh[0][0]) + k) = *(const float4*)(ab + k);
        __syncthreads();

        unsigned long long acc0[8], acc1[8];
#pragma unroll
        for (int i = 0; i < 8; i++) { acc0[i] = 0ULL; acc1[i] = 0ULL; }

#pragma unroll 4
        for (int f0 = 0; f0 < FF; f0 += 4) {
            ulonglong2 w0 = *(ulonglong2*)&w_sh[(f0 + 0) * CC + c4];
            ulonglong2 w1 = *(ulonglong2*)&w_sh[(f0 + 1) * CC + c4];
            ulonglong2 w2 = *(ulonglong2*)&w_sh[(f0 + 2) * CC + c4];
            ulonglong2 w3 = *(ulonglong2*)&w_sh[(f0 + 3) * CC + c4];
#pragma unroll
            for (int i = 0; i < 8; i++) {
                float4 a = *(float4*)&a_sh[r8 + i][f0];
                unsigned long long ax = pack2(a.x), ay = pack2(a.y);
                unsigned long long az = pack2(a.z), aw = pack2(a.w);
                ffma2(acc0[i], ax, w0.x); ffma2(acc1[i], ax, w0.y);
                ffma2(acc0[i], ay, w1.x); ffma2(acc1[i], ay, w1.y);
                ffma2(acc0[i], az, w2.x); ffma2(acc1[i], az, w2.y);
                ffma2(acc0[i], aw, w3.x); ffma2(acc1[i], aw, w3.y);
            }
        }
        __half* ob = &g_Ah[s][b][n0 + half * 64][0];
#pragma unroll
        for (int i = 0; i < 8; i++) {
            float2 p0 = unpack2(acc0[i]);
            float2 p1 = unpack2(acc1[i]);
            __half2 h01 = __floats2half2_rn(p0.x * A_SCALE, p0.y * A_SCALE);
            __half2 h23 = __floats2half2_rn(p1.x * A_SCALE, p1.y * A_SCALE);
            uint2 u = make_uint2(*(unsigned*)&h01, *(unsigned*)&h23);
            *(uint2*)&ob[(size_t)(r8 + i) * CC + c4] = u;
        }
    }
}

// Per-channel sum and sum-of-squares of z' = A'0[i0] + A'1[i1] (L2-hot gather)
__global__ void stats_kernel(const int* __restrict__ adj) {
    int tid = threadIdx.x;
    int lane = tid & 31;
    int warp_g = (blockIdx.x * blockDim.x + tid) >> 5;
    int e0 = warp_g * EP_CHUNK;
    int b = e0 / EE;                           // loop-invariant (48 | EE)
    const __half* base0 = &g_Ah[0][b][0][0];
    const __half* base1 = &g_Ah[1][b][0][0];
    const int2* ap = (const int2*)adj + e0;
    float s0 = 0, s1 = 0, s2 = 0, s3 = 0, q0 = 0, q1 = 0, q2 = 0, q3 = 0;
#pragma unroll 4
    for (int k = 0; k < EP_CHUNK; k++) {
        int2 ad = ap[k];
        const uint2* r0 = (const uint2*)(base0 + (size_t)(ad.x & (NN - 1)) * CC);
        const uint2* r1 = (const uint2*)(base1 + (size_t)(ad.y & (NN - 1)) * CC);
        uint2 u0 = r0[lane], u1 = r1[lane];
        float2 a0 = __half22float2(*(__half2*)&u0.x);
        float2 a1 = __half22float2(*(__half2*)&u0.y);
        float2 b0 = __half22float2(*(__half2*)&u1.x);
        float2 b1 = __half22float2(*(__half2*)&u1.y);
        float z;
        z = a0.x + b0.x; s0 += z; q0 = fmaf(z, z, q0);
        z = a0.y + b0.y; s1 += z; q1 = fmaf(z, z, q1);
        z = a1.x + b1.x; s2 += z; q2 = fmaf(z, z, q2);
        z = a1.y + b1.y; s3 += z; q3 = fmaf(z, z, q3);
    }
    __shared__ float sh[8 * CC];
    int w = tid >> 5;
    sh[w * CC + lane * 4 + 0] = s0;
    sh[w * CC + lane * 4 + 1] = s1;
    sh[w * CC + lane * 4 + 2] = s2;
    sh[w * CC + lane * 4 + 3] = s3;
    __syncthreads();
    if (tid < CC) {
        float t = 0;
#pragma unroll
        for (int i = 0; i < 8; i++) t += sh[i * CC + tid];
        atomicAdd(&g_sum[tid], t);
    }
    __syncthreads();
    sh[w * CC + lane * 4 + 0] = q0;
    sh[w * CC + lane * 4 + 1] = q1;
    sh[w * CC + lane * 4 + 2] = q2;
    sh[w * CC + lane * 4 + 3] = q3;
    __syncthreads();
    if (tid < CC) {
        float t = 0;
#pragma unroll
        for (int i = 0; i < 8; i++) t += sh[i * CC + tid];
        atomicAdd(&g_sq[tid], t);
    }
}

// Final pass: gather (L2-hot), BN (finalize folded in), tanh.approx, store.
__global__ void out_kernel(const int* __restrict__ adj,
                           const float* __restrict__ gamma,
                           const float* __restrict__ beta,
                           float* __restrict__ out) {
    __shared__ __align__(16) float ssc[CC];
    __shared__ __align__(16) float ssf[CC];
    int tid = threadIdx.x;
    if (tid < CC) {
        // stats were accumulated on z' = 2^14 z; unscale exactly before eps.
        float inv = 1.0f / (float)TOTAL_E;
        float mean_u = g_sum[tid] * inv * A_INVSCALE;
        float ez2_u  = g_sq[tid] * inv * (A_INVSCALE * A_INVSCALE);
        float var = fmaxf(ez2_u - mean_u * mean_u, 0.0f);
        float sc = __ldg(&gamma[tid]) * rsqrtf(var + 1e-5f);
        ssc[tid] = sc * A_INVSCALE;              // applied to scaled z'
        ssf[tid] = __ldg(&beta[tid]) - mean_u * sc;
    }
    __syncthreads();
    int lane = tid & 31;
    int warp_g = (blockIdx.x * blockDim.x + tid) >> 5;
    int e0 = warp_g * EP_CHUNK;
    int b = e0 / EE;                           // loop-invariant (48 | EE)
    const __half* base0 = &g_Ah[0][b][0][0];
    const __half* base1 = &g_Ah[1][b][0][0];
    const int2* ap = (const int2*)adj + e0;
    float* op = out + (size_t)e0 * CC + lane * 4;
    float4 sc = *(const float4*)&ssc[lane * 4];
    float4 sf = *(const float4*)&ssf[lane * 4];
#pragma unroll 4
    for (int k = 0; k < EP_CHUNK; k++) {
        int2 ad = ap[k];
        const uint2* r0 = (const uint2*)(base0 + (size_t)(ad.x & (NN - 1)) * CC);
        const uint2* r1 = (const uint2*)(base1 + (size_t)(ad.y & (NN - 1)) * CC);
        uint2 u0 = r0[lane], u1 = r1[lane];
        float2 a0 = __half22float2(*(__half2*)&u0.x);
        float2 a1 = __half22float2(*(__half2*)&u0.y);
        float2 b0 = __half22float2(*(__half2*)&u1.x);
        float2 b1 = __half22float2(*(__half2*)&u1.y);
        float4 o;
        o.x = tanh_fast(fmaf(a0.x + b0.x, sc.x, sf.x));
        o.y = tanh_fast(fmaf(a0.y + b0.y, sc.y, sf.y));
        o.z = tanh_fast(fmaf(a1.x + b1.x, sc.z, sf.z));
        o.w = tanh_fast(fmaf(a1.y + b1.y, sc.w, sf.w));
        *(float4*)(op + (size_t)k * CC) = o;
    }
}

extern "C" void kernel_launch(void* const* d_in, const int* in_sizes, int n_in,
                              void* d_out, int out_size) {
    const float* atom      = (const float*)d_in[0];
    const int*   adj       = (const int*)d_in[1];    // int32 (JAX default x64-off)
    const float* W         = (const float*)d_in[2];
    // d_in[3] (bias) is mathematically cancelled by BatchNorm -> unused
    const float* gamma     = (const float*)d_in[4];
    const float* beta      = (const float*)d_in[5];
    float* out             = (float*)d_out;

    zero_kernel<<<9, 256>>>();
    count_kernel<<<BB, 512>>>(adj);
    denom_kernel<<<128, 256>>>(atom);
    gemm_kernel<<<512, 256>>>(atom, W);
    stats_kernel<<<EP_BLOCKS, 256>>>(adj);
    out_kernel<<<EP_BLOCKS, 256>>>(adj, gamma, beta, out);
}

// round 17
// speedup vs baseline: 1.4779x; 1.2698x over previous
#include <cuda_runtime.h>
#include <cuda_fp16.h>
#include <math.h>

// Problem shapes (fixed for this dataset)
#define BB 16
#define NN 2048
#define FF 64
#define EE 24576          // edges per batch (N*M = 2048*12)
#define CC 128            // bond dim
#define TOTAL_E (BB*EE)   // 393216

#define A_SCALE 16384.0f          // 2^14 — exact; BN is affine-invariant
#define A_INVSCALE (1.0f/16384.0f)

// Edge-pass decomposition: 8192 warps * 48 edges = TOTAL_E exactly.
// 48 divides EE -> every warp's 48 edges are in ONE batch (b loop-invariant).
#define EP_BLOCKS 1024
#define EP_WARPS  (EP_BLOCKS * 8)
#define EP_CHUNK  (TOTAL_E / EP_WARPS)     // 48

// Scratch (static device globals — no runtime allocation allowed)
__device__ int    g_count[2][BB][NN];                   // overwritten each call
__device__ float  g_denp[2][BB][8][FF];                 // denom partials (overwritten)
__device__ __align__(16) __half g_Ah[2][BB][NN][CC];    // scaled fp16 GEMM results (16.7 MB, L2-hot)
__device__ float  g_sum[CC];                            // sums of scaled z' (zeroed in count)
__device__ float  g_sq[CC];                             // sums of scaled z'^2 (zeroed in count)

// ---- Blackwell packed-f32 helpers -----------------------------------------
__device__ __forceinline__ void ffma2(unsigned long long& d,
                                      unsigned long long a, unsigned long long b) {
    asm("fma.rn.f32x2 %0, %1, %2, %0;" : "+l"(d) : "l"(a), "l"(b));
}
__device__ __forceinline__ unsigned long long pack2(float x) {
    unsigned long long r;
    asm("mov.b64 %0, {%1, %1};" : "=l"(r) : "f"(x));
    return r;
}
__device__ __forceinline__ float2 unpack2(unsigned long long v) {
    float2 f;
    asm("mov.b64 {%0, %1}, %2;" : "=f"(f.x), "=f"(f.y) : "l"(v));
    return f;
}
__device__ __forceinline__ float tanh_fast(float x) {
    asm("tanh.approx.f32 %0, %0;" : "+f"(x));
    return x;
}
__device__ __forceinline__ void stcs128(float* p, float4 v) {
    asm volatile("st.global.cs.v4.f32 [%0], {%1, %2, %3, %4};"
                 :: "l"(p), "f"(v.x), "f"(v.y), "f"(v.z), "f"(v.w) : "memory");
}

// ---------------------------------------------------------------------------
// Per-batch shared-memory histogram; bulk store, no global atomics.
// Block 0's spare work: zero g_sum/g_sq (runs before stats_kernel).
__global__ void count_kernel(const int* __restrict__ adj) {
    __shared__ int h[2][NN];
    int b = blockIdx.x;
    int tid = threadIdx.x;
    if (b == 0 && tid < CC) { g_sum[tid] = 0.f; g_sq[tid] = 0.f; }
    for (int i = tid; i < 2 * NN; i += 512) (&h[0][0])[i] = 0;
    __syncthreads();
    const int2* ap = (const int2*)adj + (size_t)b * EE;
    for (int k = tid; k < EE; k += 512) {
        int2 ad = ap[k];
        atomicAdd(&h[0][ad.x & (NN - 1)], 1);
        atomicAdd(&h[1][ad.y & (NN - 1)], 1);
    }
    __syncthreads();
    for (int i = tid; i < NN; i += 512) {
        g_count[0][b][i] = h[0][i];
        g_count[1][b][i] = h[1][i];
    }
}

// Both-slot partial denominators: grid = 16*8 = 128 blocks, 256 nodes each.
// Writes partial slot [part] directly — no atomics, no pre-zeroing.
__global__ void denom_kernel(const float* __restrict__ atom) {
    int bx = blockIdx.x;
    int part = bx & 7, b = bx >> 3;
    int tid = threadIdx.x;
    int f = tid & 63, sub = tid >> 6;        // 4 row sub-partitions
    int nbase = part * 256;
    float acc0 = 0.f, acc1 = 0.f;
    const float* ab = atom + ((size_t)b * NN + nbase) * FF;
    for (int n = sub; n < 256; n += 4) {
        float v = fabsf(ab[n * FF + f]);
        int c0 = g_count[0][b][nbase + n];
        int c1 = g_count[1][b][nbase + n];
        acc0 += (float)c0 * v;
        acc1 += (float)c1 * v;
    }
    __shared__ float sh[2][256];
    sh[0][tid] = acc0;
    sh[1][tid] = acc1;
    __syncthreads();
    if (tid < 64) {
        g_denp[0][b][part][tid] =
            sh[0][tid] + sh[0][tid + 64] + sh[0][tid + 128] + sh[0][tid + 192];
    } else if (tid < 128) {
        int ff = tid - 64;
        g_denp[1][b][part][ff] =
            sh[1][ff] + sh[1][ff + 64] + sh[1][ff + 128] + sh[1][ff + 192];
    }
}

// A'_s[b,n,c] = A_SCALE * sum_f atom[b,n,f] * (W[s*64+f,c] / den_s[b,f])
// R8 configuration: grid 1024, 256 thr, 8 rows/warp, packed fma.rn.f32x2.
__global__ void gemm_kernel(const float* __restrict__ atom, const float* __restrict__ W) {
    int bx = blockIdx.x;
    int tile = bx & 31, s = (bx >> 5) & 1, b = bx >> 6;
    int n0 = tile * 64;
    __shared__ __align__(16) float a_sh[64][FF];       // 16 KB
    __shared__ __align__(16) float w_sh[FF * CC];      // 32 KB
    __shared__ float rsh[FF];
    int tid = threadIdx.x;

    if (tid < FF) {
        const float* dp = &g_denp[s][b][0][tid];
        float d = 0.f;
#pragma unroll
        for (int p = 0; p < 8; p++) d += dp[p * FF];
        rsh[tid] = 1.0f / fmaxf(d, 1e-12f);
    }
    __syncthreads();
    const float* wb = W + s * FF * CC;
#pragma unroll
    for (int k = tid * 4; k < FF * CC; k += 1024) {
        float4 wv = *(const float4*)&wb[k];
        float r = rsh[k >> 7];
        wv.x *= r; wv.y *= r; wv.z *= r; wv.w *= r;
        *(float4*)&w_sh[k] = wv;
    }
    const float* ab = atom + ((size_t)b * NN + n0) * FF;
#pragma unroll
    for (int k = tid * 4; k < 64 * FF; k += 1024)
        *(float4*)((&a_sh[0][0]) + k) = *(const float4*)(ab + k);
    __syncthreads();

    int c4 = (tid & 31) * 4;     // column slice (4 channels = 2 packed pairs)
    int r8 = (tid >> 5) * 8;     // row base per warp
    unsigned long long acc0[8], acc1[8];
#pragma unroll
    for (int i = 0; i < 8; i++) { acc0[i] = 0ULL; acc1[i] = 0ULL; }

#pragma unroll 4
    for (int f0 = 0; f0 < FF; f0 += 4) {
        ulonglong2 w0 = *(ulonglong2*)&w_sh[(f0 + 0) * CC + c4];
        ulonglong2 w1 = *(ulonglong2*)&w_sh[(f0 + 1) * CC + c4];
        ulonglong2 w2 = *(ulonglong2*)&w_sh[(f0 + 2) * CC + c4];
        ulonglong2 w3 = *(ulonglong2*)&w_sh[(f0 + 3) * CC + c4];
#pragma unroll
        for (int i = 0; i < 8; i++) {
            float4 a = *(float4*)&a_sh[r8 + i][f0];
            unsigned long long ax = pack2(a.x), ay = pack2(a.y);
            unsigned long long az = pack2(a.z), aw = pack2(a.w);
            ffma2(acc0[i], ax, w0.x); ffma2(acc1[i], ax, w0.y);
            ffma2(acc0[i], ay, w1.x); ffma2(acc1[i], ay, w1.y);
            ffma2(acc0[i], az, w2.x); ffma2(acc1[i], az, w2.y);
            ffma2(acc0[i], aw, w3.x); ffma2(acc1[i], aw, w3.y);
        }
    }
    __half* ob = &g_Ah[s][b][n0][0];
#pragma unroll
    for (int i = 0; i < 8; i++) {
        float2 p0 = unpack2(acc0[i]);
        float2 p1 = unpack2(acc1[i]);
        __half2 h01 = __floats2half2_rn(p0.x * A_SCALE, p0.y * A_SCALE);
        __half2 h23 = __floats2half2_rn(p1.x * A_SCALE, p1.y * A_SCALE);
        uint2 u = make_uint2(*(unsigned*)&h01, *(unsigned*)&h23);
        *(uint2*)&ob[(size_t)(r8 + i) * CC + c4] = u;
    }
}

// Per-channel sum and sum-of-squares of z' = A'0[i0] + A'1[i1] (L2-hot gather)
__global__ void stats_kernel(const int* __restrict__ adj) {
    int tid = threadIdx.x;
    int lane = tid & 31;
    int warp_g = (blockIdx.x * blockDim.x + tid) >> 5;
    int e0 = warp_g * EP_CHUNK;
    int b = e0 / EE;                           // loop-invariant (48 | EE)
    const __half* base0 = &g_Ah[0][b][0][0];
    const __half* base1 = &g_Ah[1][b][0][0];
    const int2* ap = (const int2*)adj + e0;
    float s0 = 0, s1 = 0, s2 = 0, s3 = 0, q0 = 0, q1 = 0, q2 = 0, q3 = 0;
#pragma unroll 4
    for (int k = 0; k < EP_CHUNK; k++) {
        int2 ad = ap[k];
        const uint2* r0 = (const uint2*)(base0 + (size_t)(ad.x & (NN - 1)) * CC);
        const uint2* r1 = (const uint2*)(base1 + (size_t)(ad.y & (NN - 1)) * CC);
        uint2 u0 = r0[lane], u1 = r1[lane];
        float2 a0 = __half22float2(*(__half2*)&u0.x);
        float2 a1 = __half22float2(*(__half2*)&u0.y);
        float2 b0 = __half22float2(*(__half2*)&u1.x);
        float2 b1 = __half22float2(*(__half2*)&u1.y);
        float z;
        z = a0.x + b0.x; s0 += z; q0 = fmaf(z, z, q0);
        z = a0.y + b0.y; s1 += z; q1 = fmaf(z, z, q1);
        z = a1.x + b1.x; s2 += z; q2 = fmaf(z, z, q2);
        z = a1.y + b1.y; s3 += z; q3 = fmaf(z, z, q3);
    }
    __shared__ float sh[8 * CC];
    int w = tid >> 5;
    sh[w * CC + lane * 4 + 0] = s0;
    sh[w * CC + lane * 4 + 1] = s1;
    sh[w * CC + lane * 4 + 2] = s2;
    sh[w * CC + lane * 4 + 3] = s3;
    __syncthreads();
    if (tid < CC) {
        float t = 0;
#pragma unroll
        for (int i = 0; i < 8; i++) t += sh[i * CC + tid];
        atomicAdd(&g_sum[tid], t);
    }
    __syncthreads();
    sh[w * CC + lane * 4 + 0] = q0;
    sh[w * CC + lane * 4 + 1] = q1;
    sh[w * CC + lane * 4 + 2] = q2;
    sh[w * CC + lane * 4 + 3] = q3;
    __syncthreads();
    if (tid < CC) {
        float t = 0;
#pragma unroll
        for (int i = 0; i < 8; i++) t += sh[i * CC + tid];
        atomicAdd(&g_sq[tid], t);
    }
}

// Final pass: gather (L2-hot), BN (finalize folded in), tanh.approx,
// streaming (evict-first) stores so the 201MB output stream doesn't evict g_Ah.
__global__ void out_kernel(const int* __restrict__ adj,
                           const float* __restrict__ gamma,
                           const float* __restrict__ beta,
                           float* __restrict__ out) {
    __shared__ __align__(16) float ssc[CC];
    __shared__ __align__(16) float ssf[CC];
    int tid = threadIdx.x;
    if (tid < CC) {
        // stats were accumulated on z' = 2^14 z; unscale exactly before eps.
        float inv = 1.0f / (float)TOTAL_E;
        float mean_u = g_sum[tid] * inv * A_INVSCALE;
        float ez2_u  = g_sq[tid] * inv * (A_INVSCALE * A_INVSCALE);
        float var = fmaxf(ez2_u - mean_u * mean_u, 0.0f);
        float sc = __ldg(&gamma[tid]) * rsqrtf(var + 1e-5f);
        ssc[tid] = sc * A_INVSCALE;              // applied to scaled z'
        ssf[tid] = __ldg(&beta[tid]) - mean_u * sc;
    }
    __syncthreads();
    int lane = tid & 31;
    int warp_g = (blockIdx.x * blockDim.x + tid) >> 5;
    int e0 = warp_g * EP_CHUNK;
    int b = e0 / EE;                           // loop-invariant (48 | EE)
    const __half* base0 = &g_Ah[0][b][0][0];
    const __half* base1 = &g_Ah[1][b][0][0];
    const int2* ap = (const int2*)adj + e0;
    float* op = out + (size_t)e0 * CC + lane * 4;
    float4 sc = *(const float4*)&ssc[lane * 4];
    float4 sf = *(const float4*)&ssf[lane * 4];
#pragma unroll 4
    for (int k = 0; k < EP_CHUNK; k++) {
        int2 ad = ap[k];
        const uint2* r0 = (const uint2*)(base0 + (size_t)(ad.x & (NN - 1)) * CC);
        const uint2* r1 = (const uint2*)(base1 + (size_t)(ad.y & (NN - 1)) * CC);
        uint2 u0 = r0[lane], u1 = r1[lane];
        float2 a0 = __half22float2(*(__half2*)&u0.x);
        float2 a1 = __half22float2(*(__half2*)&u0.y);
        float2 b0 = __half22float2(*(__half2*)&u1.x);
        float2 b1 = __half22float2(*(__half2*)&u1.y);
        float4 o;
        o.x = tanh_fast(fmaf(a0.x + b0.x, sc.x, sf.x));
        o.y = tanh_fast(fmaf(a0.y + b0.y, sc.y, sf.y));
        o.z = tanh_fast(fmaf(a1.x + b1.x, sc.z, sf.z));
        o.w = tanh_fast(fmaf(a1.y + b1.y, sc.w, sf.w));
        stcs128(op + (size_t)k * CC, o);
    }
}

extern "C" void kernel_launch(void* const* d_in, const int* in_sizes, int n_in,
                              void* d_out, int out_size) {
    const float* atom      = (const float*)d_in[0];
    const int*   adj       = (const int*)d_in[1];    // int32 (JAX default x64-off)
    const float* W         = (const float*)d_in[2];
    // d_in[3] (bias) is mathematically cancelled by BatchNorm -> unused
    const float* gamma     = (const float*)d_in[4];
    const float* beta      = (const float*)d_in[5];
    float* out             = (float*)d_out;

    count_kernel<<<BB, 512>>>(adj);
    denom_kernel<<<128, 256>>>(atom);
    gemm_kernel<<<1024, 256>>>(atom, W);
    stats_kernel<<<EP_BLOCKS, 256>>>(adj);
    out_kernel<<<EP_BLOCKS, 256>>>(adj, gamma, beta, out);
}